// round 3
// baseline (speedup 1.0000x reference)
#include <cuda_runtime.h>
#include <math.h>

#define N_NODES 50000
#define E_EDGES 800000
#define ETOT    (E_EDGES + N_NODES)   // 850000
#define F_IN    128
#define HID     64
#define HEADS   4
#define C1      (HEADS * HID)         // 256
#define SLOPE   0.2f
#define EPS_SM  1e-16f

// ------------------------- device scratch (no allocs allowed) ---------------
__device__ float g_h1  [(size_t)N_NODES * C1];
__device__ float g_out1[(size_t)N_NODES * C1];    // aggregated layer1 -> x2 after LN/ELU
__device__ float g_h2  [(size_t)N_NODES * HID];
__device__ float g_out2[(size_t)N_NODES * HID];
__device__ float g_s1  [N_NODES * HEADS];
__device__ float g_d1  [N_NODES * HEADS];
__device__ float g_den1[N_NODES * HEADS];
__device__ float g_s2  [N_NODES];
__device__ float g_d2  [N_NODES];
__device__ float g_den2[N_NODES];
// fallback alpha scratch in case d_out layout differs from expectation
__device__ float g_a1_fb[(size_t)ETOT * HEADS];
__device__ float g_a2_fb[(size_t)ETOT];

// ------------------------- helpers ------------------------------------------
__device__ __forceinline__ float lrelu(float v) { return v > 0.f ? v : SLOPE * v; }
__device__ __forceinline__ float eluf(float v)  { return v > 0.f ? v : expm1f(v); }

__device__ __forceinline__ float wredsum(float v) {
#pragma unroll
    for (int o = 16; o > 0; o >>= 1) v += __shfl_xor_sync(0xffffffffu, v, o);
    return v;
}

__device__ __forceinline__ void red_add4(float* p, float4 v) {
    asm volatile("red.global.add.v4.f32 [%0], {%1,%2,%3,%4};"
                 :: "l"(p), "f"(v.x), "f"(v.y), "f"(v.z), "f"(v.w) : "memory");
}
__device__ __forceinline__ void red_add2(float* p, float2 v) {
    asm volatile("red.global.add.v2.f32 [%0], {%1,%2};"
                 :: "l"(p), "f"(v.x), "f"(v.y) : "memory");
}

// ------------------------- zero scratch (per replay) ------------------------
__global__ void zero_scratch() {
    int i  = blockIdx.x * blockDim.x + threadIdx.x;
    size_t i4 = (size_t)i * 4;
    if (i4 < (size_t)N_NODES * C1)  *reinterpret_cast<float4*>(&g_out1[i4]) = make_float4(0,0,0,0);
    if (i4 < (size_t)N_NODES * HID) *reinterpret_cast<float4*>(&g_out2[i4]) = make_float4(0,0,0,0);
    if (i4 < (size_t)N_NODES * HEADS) *reinterpret_cast<float4*>(&g_den1[i4]) = make_float4(0,0,0,0);
    if (i4 < (size_t)N_NODES)       *reinterpret_cast<float4*>(&g_den2[i4]) = make_float4(0,0,0,0);
}

// ------------------------- GEMM: Y[r, 0:NCOLS] = X[r, 0:K] @ W[K, NCOLS] ----
template<int K, int NCOLS, int COLG, int ROWG>
__global__ __launch_bounds__(COLG * ROWG)
void gemm_kernel(const float* __restrict__ X, const float* __restrict__ W,
                 float* __restrict__ Y, int nrows) {
    constexpr int TM = ROWG * 4;
    constexpr int NT = COLG * ROWG;
    __shared__ float xs[TM * K];

    int tid     = threadIdx.x;
    int rowbase = blockIdx.x * TM;
    for (int i = tid; i < TM * K; i += NT) {
        int r = i / K, c = i - r * K;
        int gr = rowbase + r;
        xs[i] = (gr < nrows) ? X[(size_t)gr * K + c] : 0.f;
    }
    __syncthreads();

    int tx = tid % COLG, ty = tid / COLG;
    int c0 = tx * 4;
    float acc[4][4];
#pragma unroll
    for (int i = 0; i < 4; i++)
#pragma unroll
        for (int j = 0; j < 4; j++) acc[i][j] = 0.f;

#pragma unroll 4
    for (int k = 0; k < K; k++) {
        float4 w = *reinterpret_cast<const float4*>(&W[(size_t)k * NCOLS + c0]);
#pragma unroll
        for (int i = 0; i < 4; i++) {
            float a = xs[(ty * 4 + i) * K + k];
            acc[i][0] += a * w.x; acc[i][1] += a * w.y;
            acc[i][2] += a * w.z; acc[i][3] += a * w.w;
        }
    }
#pragma unroll
    for (int i = 0; i < 4; i++) {
        int gr = rowbase + ty * 4 + i;
        if (gr < nrows)
            *reinterpret_cast<float4*>(&Y[(size_t)gr * NCOLS + c0]) =
                make_float4(acc[i][0], acc[i][1], acc[i][2], acc[i][3]);
    }
}

// ------------------------- per-node attention logits ------------------------
__global__ void sd1_kernel(const float* __restrict__ asrc, const float* __restrict__ adst) {
    int idx = blockIdx.x * blockDim.x + threadIdx.x;
    if (idx >= N_NODES * HEADS) return;
    int n = idx >> 2, h = idx & 3;
    const float4* hp = reinterpret_cast<const float4*>(&g_h1[(size_t)n * C1 + h * HID]);
    const float4* as = reinterpret_cast<const float4*>(&asrc[h * HID]);
    const float4* ad = reinterpret_cast<const float4*>(&adst[h * HID]);
    float ss = 0.f, dd = 0.f;
#pragma unroll
    for (int i = 0; i < HID / 4; i++) {
        float4 v = hp[i], a = as[i], b = ad[i];
        ss += v.x * a.x + v.y * a.y + v.z * a.z + v.w * a.w;
        dd += v.x * b.x + v.y * b.y + v.z * b.z + v.w * b.w;
    }
    g_s1[idx] = ss; g_d1[idx] = dd;
}

__global__ void sd2_kernel(const float* __restrict__ asrc, const float* __restrict__ adst) {
    int n = blockIdx.x * blockDim.x + threadIdx.x;
    if (n >= N_NODES) return;
    const float4* hp = reinterpret_cast<const float4*>(&g_h2[(size_t)n * HID]);
    const float4* as = reinterpret_cast<const float4*>(asrc);
    const float4* ad = reinterpret_cast<const float4*>(adst);
    float ss = 0.f, dd = 0.f;
#pragma unroll
    for (int i = 0; i < HID / 4; i++) {
        float4 v = hp[i], a = as[i], b = ad[i];
        ss += v.x * a.x + v.y * a.y + v.z * a.z + v.w * a.w;
        dd += v.x * b.x + v.y * b.y + v.z * b.z + v.w * b.w;
    }
    g_s2[n] = ss; g_d2[n] = dd;
}

// ------------------------- layer 1 edge passes -------------------------------
__global__ void edge1a_kernel(const int* __restrict__ ei, float* __restrict__ a1) {
    int e = blockIdx.x * blockDim.x + threadIdx.x;
    if (e >= ETOT) return;
    int src, dst;
    if (e < E_EDGES) { src = ei[e]; dst = ei[E_EDGES + e]; }
    else             { src = dst = e - E_EDGES; }
    float4 s = *reinterpret_cast<const float4*>(&g_s1[src * 4]);
    float4 d = *reinterpret_cast<const float4*>(&g_d1[dst * 4]);
    float4 t;
    t.x = __expf(lrelu(s.x + d.x));
    t.y = __expf(lrelu(s.y + d.y));
    t.z = __expf(lrelu(s.z + d.z));
    t.w = __expf(lrelu(s.w + d.w));
    *reinterpret_cast<float4*>(&a1[(size_t)e * 4]) = t;
    red_add4(&g_den1[dst * 4], t);
}

__global__ void edge1b_kernel(const int* __restrict__ ei, float* __restrict__ a1) {
    int gt = blockIdx.x * blockDim.x + threadIdx.x;
    int e = gt >> 5, lane = gt & 31;
    if (e >= ETOT) return;
    int src, dst;
    if (e < E_EDGES) { src = ei[e]; dst = ei[E_EDGES + e]; }
    else             { src = dst = e - E_EDGES; }
    float4 t  = *reinterpret_cast<const float4*>(&a1[(size_t)e * 4]);
    float4 dn = *reinterpret_cast<const float4*>(&g_den1[dst * 4]);
    float4 al = make_float4(t.x / (dn.x + EPS_SM), t.y / (dn.y + EPS_SM),
                            t.z / (dn.z + EPS_SM), t.w / (dn.w + EPS_SM));
    if (lane == 0) *reinterpret_cast<float4*>(&a1[(size_t)e * 4]) = al;
    int h = lane >> 3;                               // 8 lanes per head
    float a = (h == 0) ? al.x : (h == 1) ? al.y : (h == 2) ? al.z : al.w;
    const float4* hp = reinterpret_cast<const float4*>(&g_h1[(size_t)src * C1 + lane * 8]);
    float4 v0 = hp[0], v1 = hp[1];
    float* ob = &g_out1[(size_t)dst * C1 + lane * 8];
    red_add4(ob,     make_float4(v0.x * a, v0.y * a, v0.z * a, v0.w * a));
    red_add4(ob + 4, make_float4(v1.x * a, v1.y * a, v1.z * a, v1.w * a));
}

// ------------------------- LN + ELU over 256 (in place) ---------------------
__global__ void ln1_kernel(const float* __restrict__ b1,
                           const float* __restrict__ gam, const float* __restrict__ bet) {
    int gt = blockIdx.x * blockDim.x + threadIdx.x;
    int n = gt >> 5, lane = gt & 31;
    if (n >= N_NODES) return;
    float4* row = reinterpret_cast<float4*>(&g_out1[(size_t)n * C1]);
    int c0 = lane * 4, c1 = 128 + lane * 4;
    float4 a = row[lane], b = row[lane + 32];
    float4 ba = *reinterpret_cast<const float4*>(&b1[c0]);
    float4 bb = *reinterpret_cast<const float4*>(&b1[c1]);
    a.x += ba.x; a.y += ba.y; a.z += ba.z; a.w += ba.w;
    b.x += bb.x; b.y += bb.y; b.z += bb.z; b.w += bb.w;
    float sum = a.x + a.y + a.z + a.w + b.x + b.y + b.z + b.w;
    float sq  = a.x*a.x + a.y*a.y + a.z*a.z + a.w*a.w +
                b.x*b.x + b.y*b.y + b.z*b.z + b.w*b.w;
    sum = wredsum(sum); sq = wredsum(sq);
    float mu  = sum * (1.f / 256.f);
    float var = sq * (1.f / 256.f) - mu * mu;
    float rs  = rsqrtf(var + 1e-5f);
    float4 ga = *reinterpret_cast<const float4*>(&gam[c0]);
    float4 gb = *reinterpret_cast<const float4*>(&gam[c1]);
    float4 ea = *reinterpret_cast<const float4*>(&bet[c0]);
    float4 eb = *reinterpret_cast<const float4*>(&bet[c1]);
    float4 ya, yb;
    ya.x = eluf((a.x - mu) * rs * ga.x + ea.x);
    ya.y = eluf((a.y - mu) * rs * ga.y + ea.y);
    ya.z = eluf((a.z - mu) * rs * ga.z + ea.z);
    ya.w = eluf((a.w - mu) * rs * ga.w + ea.w);
    yb.x = eluf((b.x - mu) * rs * gb.x + eb.x);
    yb.y = eluf((b.y - mu) * rs * gb.y + eb.y);
    yb.z = eluf((b.z - mu) * rs * gb.z + eb.z);
    yb.w = eluf((b.w - mu) * rs * gb.w + eb.w);
    row[lane] = ya; row[lane + 32] = yb;
}

// ------------------------- layer 2 edge passes -------------------------------
__global__ void edge2a_kernel(const int* __restrict__ ei, float* __restrict__ a2) {
    int e = blockIdx.x * blockDim.x + threadIdx.x;
    if (e >= ETOT) return;
    int src, dst;
    if (e < E_EDGES) { src = ei[e]; dst = ei[E_EDGES + e]; }
    else             { src = dst = e - E_EDGES; }
    float t = __expf(lrelu(g_s2[src] + g_d2[dst]));
    a2[e] = t;
    atomicAdd(&g_den2[dst], t);
}

__global__ void edge2b_kernel(const int* __restrict__ ei, float* __restrict__ a2) {
    int gt = blockIdx.x * blockDim.x + threadIdx.x;
    int e = gt >> 5, lane = gt & 31;
    if (e >= ETOT) return;
    int src, dst;
    if (e < E_EDGES) { src = ei[e]; dst = ei[E_EDGES + e]; }
    else             { src = dst = e - E_EDGES; }
    float t  = a2[e];
    float al = t / (g_den2[dst] + EPS_SM);
    if (lane == 0) a2[e] = al;
    float2 v = *reinterpret_cast<const float2*>(&g_h2[(size_t)src * HID + lane * 2]);
    red_add2(&g_out2[(size_t)dst * HID + lane * 2], make_float2(v.x * al, v.y * al));
}

// ------------------------- LN + ELU (64) + MLP head --------------------------
__global__ __launch_bounds__(128)
void head_kernel(const float* __restrict__ b2,
                 const float* __restrict__ g2, const float* __restrict__ e2,
                 const float* __restrict__ hW1, const float* __restrict__ hb1,
                 const float* __restrict__ hW2, const float* __restrict__ hb2,
                 float* __restrict__ out) {
    __shared__ float w1s[64 * 32];
    __shared__ float w2s[32];
    __shared__ float b1s[32];
    __shared__ float zs[4][64];
    int tid = threadIdx.x;
    for (int i = tid; i < 64 * 32; i += 128) w1s[i] = hW1[i];
    if (tid < 32) { w2s[tid] = hW2[tid]; b1s[tid] = hb1[tid]; }
    __syncthreads();

    int w = tid >> 5, lane = tid & 31;
    int n = blockIdx.x * 4 + w;
    if (n >= N_NODES) return;

    float2 v = *reinterpret_cast<const float2*>(&g_out2[(size_t)n * HID + lane * 2]);
    v.x += b2[lane * 2]; v.y += b2[lane * 2 + 1];
    float sum = wredsum(v.x + v.y);
    float sq  = wredsum(v.x * v.x + v.y * v.y);
    float mu  = sum * (1.f / 64.f);
    float var = sq * (1.f / 64.f) - mu * mu;
    float rs  = rsqrtf(var + 1e-5f);
    float y0 = eluf((v.x - mu) * rs * g2[lane * 2]     + e2[lane * 2]);
    float y1 = eluf((v.y - mu) * rs * g2[lane * 2 + 1] + e2[lane * 2 + 1]);
    zs[w][lane * 2] = y0; zs[w][lane * 2 + 1] = y1;
    __syncwarp();

    float acc = b1s[lane];
#pragma unroll
    for (int k = 0; k < 64; k++) acc += zs[w][k] * w1s[k * 32 + lane];
    acc = fmaxf(acc, 0.f);
    float p = wredsum(acc * w2s[lane]);
    if (lane == 0) out[n] = p + hb2[0];
}

// ------------------------- host launcher -------------------------------------
extern "C" void kernel_launch(void* const* d_in, const int* in_sizes, int n_in,
                              void* d_out, int out_size) {
    const float* x     = (const float*)d_in[0];
    const int*   ei    = (const int*)  d_in[1];
    const float* W1    = (const float*)d_in[2];
    const float* as1   = (const float*)d_in[3];
    const float* ad1   = (const float*)d_in[4];
    const float* b1    = (const float*)d_in[5];
    const float* W2    = (const float*)d_in[6];
    const float* as2   = (const float*)d_in[7];
    const float* ad2   = (const float*)d_in[8];
    const float* b2    = (const float*)d_in[9];
    const float* ln1g  = (const float*)d_in[10];
    const float* ln1b  = (const float*)d_in[11];
    const float* ln2g  = (const float*)d_in[12];
    const float* ln2b  = (const float*)d_in[13];
    const float* hW1   = (const float*)d_in[14];
    const float* hb1   = (const float*)d_in[15];
    const float* hW2   = (const float*)d_in[16];
    const float* hb2   = (const float*)d_in[17];
    float* out = (float*)d_out;

    // expected layout: out[N] | alpha1[ETOT*4] | alpha2[ETOT]
    size_t need = (size_t)N_NODES + (size_t)ETOT * (HEADS + 1);
    float *a1, *a2;
    if ((size_t)out_size >= need) {
        a1 = out + N_NODES;
        a2 = a1 + (size_t)ETOT * HEADS;
    } else {
        void* p;
        cudaGetSymbolAddress(&p, g_a1_fb); a1 = (float*)p;
        cudaGetSymbolAddress(&p, g_a2_fb); a2 = (float*)p;
    }

    auto cdiv = [](long a, long b) { return (int)((a + b - 1) / b); };

    // 0) zero accumulators (largest range: out1, N*C1/4 float4s)
    zero_scratch<<<cdiv((long)N_NODES * C1 / 4, 256), 256>>>();

    // 1) h1 = x @ W1  (K=128, NCOLS=256): 256 thr, TM=16
    {
        void* ph; cudaGetSymbolAddress(&ph, g_h1);
        gemm_kernel<128, 256, 64, 4><<<cdiv(N_NODES, 16), 256>>>(x, W1, (float*)ph, N_NODES);
    }
    // 2) per-node logits
    sd1_kernel<<<cdiv(N_NODES * HEADS, 256), 256>>>(as1, ad1);
    // 3) edge softmax numerators + denominators
    edge1a_kernel<<<cdiv(ETOT, 256), 256>>>(ei, a1);
    // 4) normalize + scatter-aggregate (warp per edge)
    edge1b_kernel<<<cdiv((long)ETOT * 32, 256), 256>>>(ei, a1);
    // 5) +b1, LayerNorm(256), ELU in place -> x2
    ln1_kernel<<<cdiv((long)N_NODES * 32, 256), 256>>>(b1, ln1g, ln1b);
    // 6) h2 = x2 @ W2 (K=256, NCOLS=64): 128 thr, TM=32
    {
        void *px2, *ph2;
        cudaGetSymbolAddress(&px2, g_out1);
        cudaGetSymbolAddress(&ph2, g_h2);
        gemm_kernel<256, 64, 16, 8><<<cdiv(N_NODES, 32), 128>>>((const float*)px2, W2, (float*)ph2, N_NODES);
    }
    // 7) layer-2 logits
    sd2_kernel<<<cdiv(N_NODES, 256), 256>>>(as2, ad2);
    // 8) layer-2 edge passes
    edge2a_kernel<<<cdiv(ETOT, 256), 256>>>(ei, a2);
    edge2b_kernel<<<cdiv((long)ETOT * 32, 256), 256>>>(ei, a2);
    // 9) +b2, LN(64), ELU, MLP head -> out[N]
    head_kernel<<<cdiv(N_NODES, 4), 128>>>(b2, ln2g, ln2b, hW1, hb1, hW2, hb2, out);
}

// round 4
// speedup vs baseline: 1.2137x; 1.2137x over previous
#include <cuda_runtime.h>
#include <math.h>

#define N_NODES 50000
#define E_EDGES 800000
#define ETOT    (E_EDGES + N_NODES)   // 850000
#define F_IN    128
#define HID     64
#define HEADS   4
#define C1      (HEADS * HID)         // 256
#define SLOPE   0.2f
#define EPS_SM  1e-16f

// ------------------------- device scratch (no allocs allowed) ---------------
__device__ float g_h1  [(size_t)N_NODES * C1];    // x @ W1
__device__ float g_x2  [(size_t)N_NODES * C1];    // layer1 output after LN/ELU
__device__ float g_h2  [(size_t)N_NODES * HID];   // x2 @ W2
__device__ float g_s1  [N_NODES * HEADS];
__device__ float g_d1  [N_NODES * HEADS];
__device__ float g_s2  [N_NODES];
__device__ float g_d2  [N_NODES];
// CSR by destination (rebuilt every launch; deterministic work)
__device__ int g_cnt   [N_NODES];
__device__ int g_rowptr[N_NODES + 1];
__device__ int g_wofs  [N_NODES];
__device__ int g_esrc  [ETOT];
__device__ int g_eid   [ETOT];
// fallback alpha scratch in case d_out layout differs from expectation
__device__ float g_a1_fb[(size_t)ETOT * HEADS];
__device__ float g_a2_fb[(size_t)ETOT];

// ------------------------- helpers ------------------------------------------
__device__ __forceinline__ float lrelu(float v) { return v > 0.f ? v : SLOPE * v; }
__device__ __forceinline__ float eluf(float v)  { return v > 0.f ? v : expm1f(v); }

__device__ __forceinline__ float wredsum(float v) {
#pragma unroll
    for (int o = 16; o > 0; o >>= 1) v += __shfl_xor_sync(0xffffffffu, v, o);
    return v;
}

// ------------------------- CSR build -----------------------------------------
__global__ void zero_cnt_kernel() {
    int i = blockIdx.x * blockDim.x + threadIdx.x;
    if (i < N_NODES) g_cnt[i] = 0;
}

__global__ void hist_kernel(const int* __restrict__ ei) {
    int e = blockIdx.x * blockDim.x + threadIdx.x;
    if (e >= ETOT) return;
    int dst = (e < E_EDGES) ? ei[E_EDGES + e] : e - E_EDGES;
    atomicAdd(&g_cnt[dst], 1);
}

__global__ __launch_bounds__(1024) void scan_kernel() {
    __shared__ int sums[1024];
    int t = threadIdx.x;
    constexpr int CH = (N_NODES + 1023) / 1024;   // 49
    int lo = t * CH;
    int hi = min(lo + CH, N_NODES);
    int local = 0;
    for (int i = lo; i < hi; i++) local += g_cnt[i];
    sums[t] = local;
    __syncthreads();
    // Hillis-Steele inclusive scan
    for (int off = 1; off < 1024; off <<= 1) {
        int v = (t >= off) ? sums[t - off] : 0;
        __syncthreads();
        sums[t] += v;
        __syncthreads();
    }
    int run = sums[t] - local;                    // exclusive prefix
    for (int i = lo; i < hi; i++) {
        g_rowptr[i] = run;
        g_wofs[i]   = run;
        run += g_cnt[i];
    }
    if (t == 1023) g_rowptr[N_NODES] = ETOT;
}

__global__ void scatter_kernel(const int* __restrict__ ei) {
    int e = blockIdx.x * blockDim.x + threadIdx.x;
    if (e >= ETOT) return;
    int src, dst;
    if (e < E_EDGES) { src = ei[e]; dst = ei[E_EDGES + e]; }
    else             { src = dst = e - E_EDGES; }
    int slot = atomicAdd(&g_wofs[dst], 1);
    g_esrc[slot] = src;
    g_eid[slot]  = e;
}

// ------------------------- GEMM: Y[r, 0:NCOLS] = X[r, 0:K] @ W[K, NCOLS] ----
template<int K, int NCOLS, int COLG, int ROWG>
__global__ __launch_bounds__(COLG * ROWG)
void gemm_kernel(const float* __restrict__ X, const float* __restrict__ W,
                 float* __restrict__ Y, int nrows) {
    constexpr int TM = ROWG * 4;
    constexpr int NT = COLG * ROWG;
    __shared__ float xs[TM * K];

    int tid     = threadIdx.x;
    int rowbase = blockIdx.x * TM;
    for (int i = tid; i < TM * K; i += NT) {
        int r = i / K, c = i - r * K;
        int gr = rowbase + r;
        xs[i] = (gr < nrows) ? X[(size_t)gr * K + c] : 0.f;
    }
    __syncthreads();

    int tx = tid % COLG, ty = tid / COLG;
    int c0 = tx * 4;
    float acc[4][4];
#pragma unroll
    for (int i = 0; i < 4; i++)
#pragma unroll
        for (int j = 0; j < 4; j++) acc[i][j] = 0.f;

#pragma unroll 4
    for (int k = 0; k < K; k++) {
        float4 w = *reinterpret_cast<const float4*>(&W[(size_t)k * NCOLS + c0]);
#pragma unroll
        for (int i = 0; i < 4; i++) {
            float a = xs[(ty * 4 + i) * K + k];
            acc[i][0] += a * w.x; acc[i][1] += a * w.y;
            acc[i][2] += a * w.z; acc[i][3] += a * w.w;
        }
    }
#pragma unroll
    for (int i = 0; i < 4; i++) {
        int gr = rowbase + ty * 4 + i;
        if (gr < nrows)
            *reinterpret_cast<float4*>(&Y[(size_t)gr * NCOLS + c0]) =
                make_float4(acc[i][0], acc[i][1], acc[i][2], acc[i][3]);
    }
}

// ------------------------- per-node attention logits ------------------------
__global__ void sd1_kernel(const float* __restrict__ asrc, const float* __restrict__ adst) {
    int idx = blockIdx.x * blockDim.x + threadIdx.x;
    if (idx >= N_NODES * HEADS) return;
    int n = idx >> 2, h = idx & 3;
    const float4* hp = reinterpret_cast<const float4*>(&g_h1[(size_t)n * C1 + h * HID]);
    const float4* as = reinterpret_cast<const float4*>(&asrc[h * HID]);
    const float4* ad = reinterpret_cast<const float4*>(&adst[h * HID]);
    float ss = 0.f, dd = 0.f;
#pragma unroll
    for (int i = 0; i < HID / 4; i++) {
        float4 v = hp[i], a = as[i], b = ad[i];
        ss += v.x * a.x + v.y * a.y + v.z * a.z + v.w * a.w;
        dd += v.x * b.x + v.y * b.y + v.z * b.z + v.w * b.w;
    }
    g_s1[idx] = ss; g_d1[idx] = dd;
}

__global__ void sd2_kernel(const float* __restrict__ asrc, const float* __restrict__ adst) {
    int n = blockIdx.x * blockDim.x + threadIdx.x;
    if (n >= N_NODES) return;
    const float4* hp = reinterpret_cast<const float4*>(&g_h2[(size_t)n * HID]);
    const float4* as = reinterpret_cast<const float4*>(asrc);
    const float4* ad = reinterpret_cast<const float4*>(adst);
    float ss = 0.f, dd = 0.f;
#pragma unroll
    for (int i = 0; i < HID / 4; i++) {
        float4 v = hp[i], a = as[i], b = ad[i];
        ss += v.x * a.x + v.y * a.y + v.z * a.z + v.w * a.w;
        dd += v.x * b.x + v.y * b.y + v.z * b.z + v.w * b.w;
    }
    g_s2[n] = ss; g_d2[n] = dd;
}

// ------------------------- layer 1: gather-aggregate + LN + ELU (fused) ------
// one warp per destination node; acc holds the full 256-wide row (8 per lane)
__global__ __launch_bounds__(256)
void agg1_kernel(float* __restrict__ a1, const float* __restrict__ b1,
                 const float* __restrict__ gam, const float* __restrict__ bet) {
    int gw   = (blockIdx.x * blockDim.x + threadIdx.x) >> 5;
    int lane = threadIdx.x & 31;
    if (gw >= N_NODES) return;
    int n = gw;
    int base = g_rowptr[n], end = g_rowptr[n + 1];
    float4 d = *reinterpret_cast<const float4*>(&g_d1[n * 4]);

    // pass 1: softmax denominators (lane-parallel over incident edges)
    float4 den = make_float4(0.f, 0.f, 0.f, 0.f);
    for (int j = base + lane; j < end; j += 32) {
        int src = g_esrc[j];
        float4 s = *reinterpret_cast<const float4*>(&g_s1[src * 4]);
        den.x += __expf(lrelu(s.x + d.x));
        den.y += __expf(lrelu(s.y + d.y));
        den.z += __expf(lrelu(s.z + d.z));
        den.w += __expf(lrelu(s.w + d.w));
    }
    den.x = wredsum(den.x); den.y = wredsum(den.y);
    den.z = wredsum(den.z); den.w = wredsum(den.w);
    float ivx = 1.f / (den.x + EPS_SM), ivy = 1.f / (den.y + EPS_SM);
    float ivz = 1.f / (den.z + EPS_SM), ivw = 1.f / (den.w + EPS_SM);

    // pass 2: alpha + gather-accumulate (warp cooperates on 256 features)
    int h  = lane >> 3;           // head for this lane's 8-feature slice
    int c0 = lane * 8;
    float acc[8];
#pragma unroll
    for (int i = 0; i < 8; i++) acc[i] = 0.f;

    for (int j = base; j < end; j++) {
        int src = g_esrc[j];                                       // uniform
        float4 s = *reinterpret_cast<const float4*>(&g_s1[src * 4]); // broadcast
        float4 al;
        al.x = __expf(lrelu(s.x + d.x)) * ivx;
        al.y = __expf(lrelu(s.y + d.y)) * ivy;
        al.z = __expf(lrelu(s.z + d.z)) * ivz;
        al.w = __expf(lrelu(s.w + d.w)) * ivw;
        if (lane == 0)
            *reinterpret_cast<float4*>(&a1[(size_t)g_eid[j] * 4]) = al;
        float a = (h == 0) ? al.x : (h == 1) ? al.y : (h == 2) ? al.z : al.w;
        const float4* hp = reinterpret_cast<const float4*>(&g_h1[(size_t)src * C1 + c0]);
        float4 v0 = hp[0], v1 = hp[1];
        acc[0] += v0.x * a; acc[1] += v0.y * a; acc[2] += v0.z * a; acc[3] += v0.w * a;
        acc[4] += v1.x * a; acc[5] += v1.y * a; acc[6] += v1.z * a; acc[7] += v1.w * a;
    }

    // epilogue: +b1, LayerNorm(256), ELU -> g_x2
    float4 ba = *reinterpret_cast<const float4*>(&b1[c0]);
    float4 bb = *reinterpret_cast<const float4*>(&b1[c0 + 4]);
    acc[0] += ba.x; acc[1] += ba.y; acc[2] += ba.z; acc[3] += ba.w;
    acc[4] += bb.x; acc[5] += bb.y; acc[6] += bb.z; acc[7] += bb.w;
    float sum = 0.f, sq = 0.f;
#pragma unroll
    for (int i = 0; i < 8; i++) { sum += acc[i]; sq += acc[i] * acc[i]; }
    sum = wredsum(sum); sq = wredsum(sq);
    float mu  = sum * (1.f / 256.f);
    float var = sq * (1.f / 256.f) - mu * mu;
    float rs  = rsqrtf(var + 1e-5f);
    float4 ga = *reinterpret_cast<const float4*>(&gam[c0]);
    float4 gb = *reinterpret_cast<const float4*>(&gam[c0 + 4]);
    float4 ea = *reinterpret_cast<const float4*>(&bet[c0]);
    float4 eb = *reinterpret_cast<const float4*>(&bet[c0 + 4]);
    float4 y0, y1;
    y0.x = eluf((acc[0] - mu) * rs * ga.x + ea.x);
    y0.y = eluf((acc[1] - mu) * rs * ga.y + ea.y);
    y0.z = eluf((acc[2] - mu) * rs * ga.z + ea.z);
    y0.w = eluf((acc[3] - mu) * rs * ga.w + ea.w);
    y1.x = eluf((acc[4] - mu) * rs * gb.x + eb.x);
    y1.y = eluf((acc[5] - mu) * rs * gb.y + eb.y);
    y1.z = eluf((acc[6] - mu) * rs * gb.z + eb.z);
    y1.w = eluf((acc[7] - mu) * rs * gb.w + eb.w);
    float4* orow = reinterpret_cast<float4*>(&g_x2[(size_t)n * C1 + c0]);
    orow[0] = y0; orow[1] = y1;
}

// ------------------------- layer 2: gather-aggregate + LN + ELU + MLP head ---
__global__ __launch_bounds__(256)
void agg2_kernel(float* __restrict__ a2, const float* __restrict__ b2,
                 const float* __restrict__ g2, const float* __restrict__ e2,
                 const float* __restrict__ hW1, const float* __restrict__ hb1,
                 const float* __restrict__ hW2, const float* __restrict__ hb2,
                 float* __restrict__ out) {
    __shared__ float w1s[64 * 32];
    __shared__ float w2s[32];
    __shared__ float b1s[32];
    __shared__ float zs[8][64];
    int tid = threadIdx.x;
    for (int i = tid; i < 64 * 32; i += 256) w1s[i] = hW1[i];
    if (tid < 32) { w2s[tid] = hW2[tid]; b1s[tid] = hb1[tid]; }
    __syncthreads();

    int w    = tid >> 5;
    int lane = tid & 31;
    int n = blockIdx.x * 8 + w;
    if (n >= N_NODES) return;

    int base = g_rowptr[n], end = g_rowptr[n + 1];
    float dd = g_d2[n];

    float den = 0.f;
    for (int j = base + lane; j < end; j += 32) {
        int src = g_esrc[j];
        den += __expf(lrelu(g_s2[src] + dd));
    }
    den = wredsum(den);
    float inv = 1.f / (den + EPS_SM);

    float a0 = 0.f, a1v = 0.f;
    int c0 = lane * 2;
    for (int j = base; j < end; j++) {
        int src = g_esrc[j];                                 // uniform
        float t = __expf(lrelu(g_s2[src] + dd)) * inv;
        if (lane == 0) a2[g_eid[j]] = t;
        float2 v = *reinterpret_cast<const float2*>(&g_h2[(size_t)src * HID + c0]);
        a0 += v.x * t; a1v += v.y * t;
    }

    // +b2, LN(64), ELU
    a0  += b2[c0];
    a1v += b2[c0 + 1];
    float sum = wredsum(a0 + a1v);
    float sq  = wredsum(a0 * a0 + a1v * a1v);
    float mu  = sum * (1.f / 64.f);
    float var = sq * (1.f / 64.f) - mu * mu;
    float rs  = rsqrtf(var + 1e-5f);
    float y0 = eluf((a0  - mu) * rs * g2[c0]     + e2[c0]);
    float y1 = eluf((a1v - mu) * rs * g2[c0 + 1] + e2[c0 + 1]);
    zs[w][c0] = y0; zs[w][c0 + 1] = y1;
    __syncwarp();

    // MLP head: 64 -> 32 -> ReLU -> 1
    float acc = b1s[lane];
#pragma unroll
    for (int k = 0; k < 64; k++) acc += zs[w][k] * w1s[k * 32 + lane];
    acc = fmaxf(acc, 0.f);
    float p = wredsum(acc * w2s[lane]);
    if (lane == 0) out[n] = p + hb2[0];
}

// ------------------------- host launcher -------------------------------------
extern "C" void kernel_launch(void* const* d_in, const int* in_sizes, int n_in,
                              void* d_out, int out_size) {
    const float* x     = (const float*)d_in[0];
    const int*   ei    = (const int*)  d_in[1];
    const float* W1    = (const float*)d_in[2];
    const float* as1   = (const float*)d_in[3];
    const float* ad1   = (const float*)d_in[4];
    const float* b1    = (const float*)d_in[5];
    const float* W2    = (const float*)d_in[6];
    const float* as2   = (const float*)d_in[7];
    const float* ad2   = (const float*)d_in[8];
    const float* b2    = (const float*)d_in[9];
    const float* ln1g  = (const float*)d_in[10];
    const float* ln1b  = (const float*)d_in[11];
    const float* ln2g  = (const float*)d_in[12];
    const float* ln2b  = (const float*)d_in[13];
    const float* hW1   = (const float*)d_in[14];
    const float* hb1   = (const float*)d_in[15];
    const float* hW2   = (const float*)d_in[16];
    const float* hb2   = (const float*)d_in[17];
    float* out = (float*)d_out;

    // expected layout: out[N] | alpha1[ETOT*4] | alpha2[ETOT]
    size_t need = (size_t)N_NODES + (size_t)ETOT * (HEADS + 1);
    float *a1, *a2;
    if ((size_t)out_size >= need) {
        a1 = out + N_NODES;
        a2 = a1 + (size_t)ETOT * HEADS;
    } else {
        void* p;
        cudaGetSymbolAddress(&p, g_a1_fb); a1 = (float*)p;
        cudaGetSymbolAddress(&p, g_a2_fb); a2 = (float*)p;
    }

    auto cdiv = [](long a, long b) { return (int)((a + b - 1) / b); };

    // ---- CSR build (reused by both layers) ----
    zero_cnt_kernel<<<cdiv(N_NODES, 256), 256>>>();
    hist_kernel<<<cdiv(ETOT, 256), 256>>>(ei);
    scan_kernel<<<1, 1024>>>();
    scatter_kernel<<<cdiv(ETOT, 256), 256>>>(ei);

    // ---- layer 1 ----
    {
        void* ph; cudaGetSymbolAddress(&ph, g_h1);
        gemm_kernel<128, 256, 64, 4><<<cdiv(N_NODES, 16), 256>>>(x, W1, (float*)ph, N_NODES);
    }
    sd1_kernel<<<cdiv(N_NODES * HEADS, 256), 256>>>(as1, ad1);
    agg1_kernel<<<cdiv((long)N_NODES * 32, 256), 256>>>(a1, b1, ln1g, ln1b);

    // ---- layer 2 ----
    {
        void *px2, *ph2;
        cudaGetSymbolAddress(&px2, g_x2);
        cudaGetSymbolAddress(&ph2, g_h2);
        gemm_kernel<256, 64, 16, 8><<<cdiv(N_NODES, 32), 128>>>((const float*)px2, W2, (float*)ph2, N_NODES);
    }
    sd2_kernel<<<cdiv(N_NODES, 256), 256>>>(as2, ad2);
    agg2_kernel<<<cdiv(N_NODES, 8), 256>>>(a2, b2, ln2g, ln2b, hW1, hb1, hW2, hb2, out);
}